// round 4
// baseline (speedup 1.0000x reference)
#include <cuda_runtime.h>
#include <cuda_bf16.h>

// Problem constants
#define BS1 32
#define BS2 128
#define NUM_EC 64
#define MEM_DIM 256
#define MLP_DIM 256
#define Q_DIM 256           // 4 * CONV_DIM

// Block roles within the single fused grid
#define C1_BLOCKS   256     // 32 b x 8 e-tiles of 8
#define ATT_BLOCKS  32
#define PE_BLOCKS   32
#define PREP_BLOCKS (C1_BLOCKS + ATT_BLOCKS + PE_BLOCKS)   // 320
#define P_TILE      4
#define MAIN_BLOCKS (BS1 * (BS2 / P_TILE))                  // 1024
#define E_TILE      8
#define PE_P_TILE   4

// Scratch + sync (device globals — allocation is forbidden)
__device__ float g_att[BS1 * NUM_EC];              // softmax_e(criteria·Wa_c)
__device__ float g_PC [BS1 * NUM_EC * MLP_DIM];    // raw criteria @ Wm_c
__device__ float g_PE [BS2 * MLP_DIM];             // ehr @ Wm_e
__device__ unsigned int g_done = 0;                // prep blocks completed
__device__ unsigned int g_fin  = 0;                // main blocks completed (reset)

// ---------------------------------------------------------------------------
// One fused kernel.
//   bids [0,256):    PC[b,e,d] = dot(criteria[b,e,:], Wm_c[:,d])
//   bids [256,288):  att[b,:]  = softmax_e(criteria[b,e,:]·Wa_c)
//                    (logit_e[p] + b_align constant over e -> cancel)
//   bids [288,320):  PE[p,d]   = dot(ehr[p,:], Wm_e[:,d])
//   bids [320,1344): out[b,p,e,d] = att[b,e]*(PC[b,e,d]+PE[p,d]) + b_mlp[d]
// Main blocks spin on g_done until all 320 prep blocks release.
// __launch_bounds__(256,4) guarantees >=4 blocks/SM so all 320 prep blocks
// land in wave 1 (capacity >= 592) -> no deadlock.
// ---------------------------------------------------------------------------
__global__ void __launch_bounds__(256, 4)
k_fused(const float* __restrict__ ehr,
        const float* __restrict__ crit,
        const float* __restrict__ W_align,
        const float* __restrict__ W_mlp,
        const float* __restrict__ b_mlp,
        float* __restrict__ out) {
    __shared__ __align__(16) float sbuf[2048];   // 8 KB, reused by all roles
    const int bid = blockIdx.x;
    const int tid = threadIdx.x;

    if (bid < C1_BLOCKS) {
        // ----- PC: criteria @ Wm_c (raw; att & b_mlp applied in main) -----
        const int b  = bid >> 3;
        const int e0 = (bid & 7) * E_TILE;
        const int d  = tid;

        float4* cs = (float4*)sbuf;              // [E_TILE][Q_DIM/4]
        const float4* src = (const float4*)crit + (size_t)(b * NUM_EC + e0) * (Q_DIM / 4);
        cs[tid]       = src[tid];
        cs[tid + 256] = src[tid + 256];
        __syncthreads();

        float acc[E_TILE];
        #pragma unroll
        for (int e = 0; e < E_TILE; ++e) acc[e] = 0.f;

        const float* wcol = W_mlp + d;
        #pragma unroll 4
        for (int k4 = 0; k4 < Q_DIM / 4; ++k4) {
            float w0 = wcol[(k4 * 4 + 0) * MLP_DIM];
            float w1 = wcol[(k4 * 4 + 1) * MLP_DIM];
            float w2 = wcol[(k4 * 4 + 2) * MLP_DIM];
            float w3 = wcol[(k4 * 4 + 3) * MLP_DIM];
            #pragma unroll
            for (int e = 0; e < E_TILE; ++e) {
                float4 c = cs[e * (Q_DIM / 4) + k4];   // warp-broadcast LDS
                acc[e] += c.x * w0 + c.y * w1 + c.z * w2 + c.w * w3;
            }
        }
        #pragma unroll
        for (int e = 0; e < E_TILE; ++e)
            g_PC[((size_t)(b * NUM_EC + e0 + e)) * MLP_DIM + d] = acc[e];

        __threadfence();
        __syncthreads();
        if (tid == 0) atomicAdd(&g_done, 1u);
        return;

    } else if (bid < C1_BLOCKS + ATT_BLOCKS) {
        // ----- att -----
        const int b = bid - C1_BLOCKS;
        const int e = tid >> 2;
        const int q = tid & 3;

        const float4* row = (const float4*)(crit + ((size_t)(b * NUM_EC + e)) * Q_DIM);
        const float4* wa  = (const float4*)W_align;

        float s = 0.f;
        #pragma unroll
        for (int i = 0; i < 16; ++i) {
            float4 c = row[q * 16 + i];
            float4 w = wa [q * 16 + i];
            s += c.x * w.x + c.y * w.y + c.z * w.z + c.w * w.w;
        }
        s += __shfl_xor_sync(0xffffffffu, s, 1);
        s += __shfl_xor_sync(0xffffffffu, s, 2);

        float* sm = sbuf;
        if (q == 0) sm[e] = s;
        __syncthreads();

        if (tid < 32) {
            float a  = sm[tid];
            float bb = sm[tid + 32];
            float m = fmaxf(a, bb);
            #pragma unroll
            for (int off = 16; off; off >>= 1)
                m = fmaxf(m, __shfl_xor_sync(0xffffffffu, m, off));
            float ea = expf(a - m);
            float eb = expf(bb - m);
            float ss = ea + eb;
            #pragma unroll
            for (int off = 16; off; off >>= 1)
                ss += __shfl_xor_sync(0xffffffffu, ss, off);
            float inv = 1.f / ss;
            g_att[b * NUM_EC + tid]      = ea * inv;
            g_att[b * NUM_EC + tid + 32] = eb * inv;
        }
        __threadfence();
        __syncthreads();
        if (tid == 0) atomicAdd(&g_done, 1u);
        return;

    } else if (bid < PREP_BLOCKS) {
        // ----- PE: ehr @ Wm_e -----
        const int pg = bid - (C1_BLOCKS + ATT_BLOCKS);
        const int p0 = pg * PE_P_TILE;
        const int d  = tid;

        float* es = sbuf;                        // [PE_P_TILE][MEM_DIM]
        #pragma unroll
        for (int i = 0; i < PE_P_TILE; ++i)
            es[i * MEM_DIM + d] = ehr[(size_t)(p0 + i) * MEM_DIM + d];
        __syncthreads();

        float acc[PE_P_TILE];
        #pragma unroll
        for (int i = 0; i < PE_P_TILE; ++i) acc[i] = 0.f;

        const float* w = W_mlp + (size_t)Q_DIM * MLP_DIM + d;
        #pragma unroll 4
        for (int k = 0; k < MEM_DIM; ++k) {
            float wv = w[(size_t)k * MLP_DIM];
            #pragma unroll
            for (int i = 0; i < PE_P_TILE; ++i)
                acc[i] += es[i * MEM_DIM + k] * wv;
        }
        #pragma unroll
        for (int i = 0; i < PE_P_TILE; ++i)
            g_PE[(size_t)(p0 + i) * MLP_DIM + d] = acc[i];

        __threadfence();
        __syncthreads();
        if (tid == 0) atomicAdd(&g_done, 1u);
        return;
    }

    // ===== main (store-bound) =====
    const int mbid = bid - PREP_BLOCKS;
    const int b    = mbid >> 5;
    const int pg   = mbid & 31;
    const int p0   = pg * P_TILE;
    const int v    = tid & 63;        // float4-lane within d; loop-invariant

    // Load loop-invariant operands while prep may still be running is NOT
    // safe for PE (produced by prep) — so wait first.
    if (tid == 0) {
        while (atomicAdd(&g_done, 0u) < PREP_BLOCKS) __nanosleep(128);
    }
    __syncthreads();
    __threadfence();   // acquire: order subsequent loads after the flag read

    float* atts = sbuf;               // 64 floats
    if (tid < NUM_EC) atts[tid] = g_att[b * NUM_EC + tid];
    __syncthreads();

    const float4 bm = __ldg((const float4*)b_mlp + v);
    float4 pe0 = __ldg((const float4*)g_PE + (size_t)(p0 + 0) * (MLP_DIM / 4) + v);
    float4 pe1 = __ldg((const float4*)g_PE + (size_t)(p0 + 1) * (MLP_DIM / 4) + v);
    float4 pe2 = __ldg((const float4*)g_PE + (size_t)(p0 + 2) * (MLP_DIM / 4) + v);
    float4 pe3 = __ldg((const float4*)g_PE + (size_t)(p0 + 3) * (MLP_DIM / 4) + v);

    const float4* pc = (const float4*)g_PC + (size_t)b * NUM_EC * (MLP_DIM / 4);
    float4* o = (float4*)out;
    const size_t base = (size_t)b * (BS2 * NUM_EC * (MLP_DIM / 4))
                      + (size_t)p0 * (NUM_EC * (MLP_DIM / 4));
    const int stride_p = NUM_EC * (MLP_DIM / 4);    // 4096 float4

    #pragma unroll 4
    for (int k = 0; k < 16; ++k) {
        const int i = tid + k * 256;
        const float  a = atts[i >> 6];
        const float4 c = __ldg(&pc[i]);
        float4 r0, r1, r2, r3;
        r0.x = fmaf(a, c.x + pe0.x, bm.x); r0.y = fmaf(a, c.y + pe0.y, bm.y);
        r0.z = fmaf(a, c.z + pe0.z, bm.z); r0.w = fmaf(a, c.w + pe0.w, bm.w);
        r1.x = fmaf(a, c.x + pe1.x, bm.x); r1.y = fmaf(a, c.y + pe1.y, bm.y);
        r1.z = fmaf(a, c.z + pe1.z, bm.z); r1.w = fmaf(a, c.w + pe1.w, bm.w);
        r2.x = fmaf(a, c.x + pe2.x, bm.x); r2.y = fmaf(a, c.y + pe2.y, bm.y);
        r2.z = fmaf(a, c.z + pe2.z, bm.z); r2.w = fmaf(a, c.w + pe2.w, bm.w);
        r3.x = fmaf(a, c.x + pe3.x, bm.x); r3.y = fmaf(a, c.y + pe3.y, bm.y);
        r3.z = fmaf(a, c.z + pe3.z, bm.z); r3.w = fmaf(a, c.w + pe3.w, bm.w);
        __stcs(&o[base + 0 * stride_p + i], r0);
        __stcs(&o[base + 1 * stride_p + i], r1);
        __stcs(&o[base + 2 * stride_p + i], r2);
        __stcs(&o[base + 3 * stride_p + i], r3);
    }

    // Reset sync counters for the next graph replay (last main block).
    __syncthreads();
    if (tid == 0) {
        __threadfence();
        unsigned int old = atomicAdd(&g_fin, 1u);
        if (old == MAIN_BLOCKS - 1) {
            g_done = 0;
            g_fin  = 0;
            __threadfence();
        }
    }
}

// ---------------------------------------------------------------------------
// Inputs per metadata order:
// 0: ehr_vector (128*256)  1: criteria (32*64*256)  2: ec_mask (unused)
// 3: W_align (512)         4: b_align (unused, cancels in softmax)
// 5: W_mlp (512*256)       6: b_mlp (256)
// ---------------------------------------------------------------------------
extern "C" void kernel_launch(void* const* d_in, const int* in_sizes, int n_in,
                              void* d_out, int out_size) {
    const float* ehr     = (const float*)d_in[0];
    const float* crit    = (const float*)d_in[1];
    const float* W_align = (const float*)d_in[3];
    const float* W_mlp   = (const float*)d_in[5];
    const float* b_mlp   = (const float*)d_in[6];
    float* out = (float*)d_out;

    k_fused<<<PREP_BLOCKS + MAIN_BLOCKS, 256>>>(ehr, crit, W_align, W_mlp, b_mlp, out);
}

// round 5
// speedup vs baseline: 1.1266x; 1.1266x over previous
#include <cuda_runtime.h>
#include <cuda_bf16.h>

// Problem constants
#define BS1 32
#define BS2 128
#define NUM_EC 64
#define MEM_DIM 256
#define MLP_DIM 256
#define Q_DIM 256           // 4 * CONV_DIM

// Scratch (device globals — allocation is forbidden)
__device__ float g_att[BS1 * NUM_EC];              // softmax_e(criteria·Wa_c)
__device__ float g_PC [BS1 * NUM_EC * MLP_DIM];    // raw criteria @ Wm_c
__device__ float g_PE [BS2 * MLP_DIM];             // ehr @ Wm_e

// ---------------------------------------------------------------------------
// Prep kernel (one wave, 320 blocks):
//   bids [0,256):   PC[b,e,d] = dot(criteria[b,e,:], Wm_c[:,d])
//                   32 b x 4 e-tiles(16) x 2 d-halves(128); k split x2 over
//                   threads with smem reduce. E_TILE=16 halves W_mlp L2 traffic.
//   bids [256,288): att[b,:] = softmax_e(criteria[b,e,:]·Wa_c)
//                   (logit_e[p] and b_align are constant over e -> cancel)
//   bids [288,320): PE[p,d] = dot(ehr[p,:], Wm_e[:,d])   (4 p / block)
// ---------------------------------------------------------------------------
#define C1_BLOCKS   256
#define ATT_BLOCKS  32
#define PE_BLOCKS   32
#define E_TILE      16
#define PE_P_TILE   4

__global__ void __launch_bounds__(256) k_prep(const float* __restrict__ ehr,
                                              const float* __restrict__ crit,
                                              const float* __restrict__ W_align,
                                              const float* __restrict__ W_mlp) {
    __shared__ __align__(16) float sbuf[E_TILE * Q_DIM];   // 16 KB, reused
    const int bid = blockIdx.x;
    const int tid = threadIdx.x;

    if (bid < C1_BLOCKS) {
        // ----- PC -----
        const int b  = bid >> 3;
        const int et = (bid >> 1) & 3;
        const int dh = bid & 1;
        const int e0 = et * E_TILE;
        const int dl = tid & 127;          // local d within half
        const int kh = tid >> 7;           // k-half (0/1)
        const int d  = dh * 128 + dl;

        // load criteria[b, e0..e0+15, :]  (1024 float4, 4 per thread)
        float4* cs = (float4*)sbuf;        // [E_TILE][Q_DIM/4]
        const float4* src = (const float4*)crit + (size_t)(b * NUM_EC + e0) * (Q_DIM / 4);
        #pragma unroll
        for (int i = 0; i < 4; ++i)
            cs[tid + i * 256] = src[tid + i * 256];
        __syncthreads();

        float acc[E_TILE];
        #pragma unroll
        for (int e = 0; e < E_TILE; ++e) acc[e] = 0.f;

        const float* wcol = W_mlp + d;
        const int k4base = kh * 32;        // 32 float4-groups = 128 k per half
        #pragma unroll 2
        for (int k4 = k4base; k4 < k4base + 32; ++k4) {
            float w0 = wcol[(k4 * 4 + 0) * MLP_DIM];
            float w1 = wcol[(k4 * 4 + 1) * MLP_DIM];
            float w2 = wcol[(k4 * 4 + 2) * MLP_DIM];
            float w3 = wcol[(k4 * 4 + 3) * MLP_DIM];
            #pragma unroll
            for (int e = 0; e < E_TILE; ++e) {
                float4 c = cs[e * (Q_DIM / 4) + k4];   // warp-broadcast LDS
                acc[e] += c.x * w0 + c.y * w1 + c.z * w2 + c.w * w3;
            }
        }
        __syncthreads();                   // cs fully consumed; reuse as partials
        float* part = sbuf;                // [2][E_TILE][128]
        #pragma unroll
        for (int e = 0; e < E_TILE; ++e)
            part[(kh * E_TILE + e) * 128 + dl] = acc[e];
        __syncthreads();

        // 2048 outputs, 256 threads -> 8 each (coalesced over dl)
        #pragma unroll
        for (int i = 0; i < 8; ++i) {
            const int idx = tid + i * 256;         // e*128 + dd
            const int e  = idx >> 7;
            const int dd = idx & 127;
            float v = part[e * 128 + dd] + part[(E_TILE + e) * 128 + dd];
            g_PC[((size_t)(b * NUM_EC + e0 + e)) * MLP_DIM + dh * 128 + dd] = v;
        }

    } else if (bid < C1_BLOCKS + ATT_BLOCKS) {
        // ----- att -----
        const int b = bid - C1_BLOCKS;
        const int e = tid >> 2;
        const int q = tid & 3;

        const float4* row = (const float4*)(crit + ((size_t)(b * NUM_EC + e)) * Q_DIM);
        const float4* wa  = (const float4*)W_align;

        float s = 0.f;
        #pragma unroll
        for (int i = 0; i < 16; ++i) {
            float4 c = row[q * 16 + i];
            float4 w = wa [q * 16 + i];
            s += c.x * w.x + c.y * w.y + c.z * w.z + c.w * w.w;
        }
        s += __shfl_xor_sync(0xffffffffu, s, 1);
        s += __shfl_xor_sync(0xffffffffu, s, 2);

        float* sm = sbuf;
        if (q == 0) sm[e] = s;
        __syncthreads();

        if (tid < 32) {
            float a  = sm[tid];
            float bb = sm[tid + 32];
            float m = fmaxf(a, bb);
            #pragma unroll
            for (int off = 16; off; off >>= 1)
                m = fmaxf(m, __shfl_xor_sync(0xffffffffu, m, off));
            float ea = expf(a - m);
            float eb = expf(bb - m);
            float ss = ea + eb;
            #pragma unroll
            for (int off = 16; off; off >>= 1)
                ss += __shfl_xor_sync(0xffffffffu, ss, off);
            float inv = 1.f / ss;
            g_att[b * NUM_EC + tid]      = ea * inv;
            g_att[b * NUM_EC + tid + 32] = eb * inv;
        }

    } else {
        // ----- PE -----
        const int pg = bid - (C1_BLOCKS + ATT_BLOCKS);
        const int p0 = pg * PE_P_TILE;
        const int d  = tid;

        float* es = sbuf;                  // [PE_P_TILE][MEM_DIM]
        #pragma unroll
        for (int i = 0; i < PE_P_TILE; ++i)
            es[i * MEM_DIM + d] = ehr[(size_t)(p0 + i) * MEM_DIM + d];
        __syncthreads();

        float acc[PE_P_TILE];
        #pragma unroll
        for (int i = 0; i < PE_P_TILE; ++i) acc[i] = 0.f;

        const float* w = W_mlp + (size_t)Q_DIM * MLP_DIM + d;
        #pragma unroll 4
        for (int k = 0; k < MEM_DIM; ++k) {
            float wv = w[(size_t)k * MLP_DIM];
            #pragma unroll
            for (int i = 0; i < PE_P_TILE; ++i)
                acc[i] += es[i * MEM_DIM + k] * wv;
        }
        #pragma unroll
        for (int i = 0; i < PE_P_TILE; ++i)
            g_PE[(size_t)(p0 + i) * MLP_DIM + d] = acc[i];
    }
}

// ---------------------------------------------------------------------------
// Main (store-bound): out[b,p,e,d] = att[b,e] * (PC[b,e,d] + PE[p,d]) + b_mlp[d]
// R1 configuration (fastest measured: 45.0us): grid = 32 b x 32 p-groups
// (P_TILE=4), block = 256, NO forced residency. Loop-invariant PE/b_mlp
// hoisted into registers (v = tid&63 is constant across the i-loop).
// __stcs streaming stores: output is never re-read.
// ---------------------------------------------------------------------------
#define P_TILE 4
__global__ void __launch_bounds__(256) k_main(float* __restrict__ out,
                                              const float* __restrict__ b_mlp) {
    const int b   = blockIdx.x >> 5;
    const int pg  = blockIdx.x & 31;
    const int p0  = pg * P_TILE;
    const int tid = threadIdx.x;
    const int v   = tid & 63;

    __shared__ float atts[NUM_EC];
    if (tid < NUM_EC) atts[tid] = g_att[b * NUM_EC + tid];
    __syncthreads();

    const float4 bm  = __ldg((const float4*)b_mlp + v);
    const float4 pe0 = __ldg((const float4*)g_PE + (size_t)(p0 + 0) * (MLP_DIM / 4) + v);
    const float4 pe1 = __ldg((const float4*)g_PE + (size_t)(p0 + 1) * (MLP_DIM / 4) + v);
    const float4 pe2 = __ldg((const float4*)g_PE + (size_t)(p0 + 2) * (MLP_DIM / 4) + v);
    const float4 pe3 = __ldg((const float4*)g_PE + (size_t)(p0 + 3) * (MLP_DIM / 4) + v);

    const float4* pc = (const float4*)g_PC + (size_t)b * NUM_EC * (MLP_DIM / 4);
    float4* o = (float4*)out;
    const size_t base = (size_t)b * (BS2 * NUM_EC * (MLP_DIM / 4))
                      + (size_t)p0 * (NUM_EC * (MLP_DIM / 4));
    const int stride_p = NUM_EC * (MLP_DIM / 4);    // 4096 float4

    #pragma unroll 4
    for (int k = 0; k < 16; ++k) {
        const int i = tid + k * 256;
        const float  a = atts[i >> 6];
        const float4 c = __ldg(&pc[i]);
        float4 r0, r1, r2, r3;
        r0.x = fmaf(a, c.x + pe0.x, bm.x); r0.y = fmaf(a, c.y + pe0.y, bm.y);
        r0.z = fmaf(a, c.z + pe0.z, bm.z); r0.w = fmaf(a, c.w + pe0.w, bm.w);
        r1.x = fmaf(a, c.x + pe1.x, bm.x); r1.y = fmaf(a, c.y + pe1.y, bm.y);
        r1.z = fmaf(a, c.z + pe1.z, bm.z); r1.w = fmaf(a, c.w + pe1.w, bm.w);
        r2.x = fmaf(a, c.x + pe2.x, bm.x); r2.y = fmaf(a, c.y + pe2.y, bm.y);
        r2.z = fmaf(a, c.z + pe2.z, bm.z); r2.w = fmaf(a, c.w + pe2.w, bm.w);
        r3.x = fmaf(a, c.x + pe3.x, bm.x); r3.y = fmaf(a, c.y + pe3.y, bm.y);
        r3.z = fmaf(a, c.z + pe3.z, bm.z); r3.w = fmaf(a, c.w + pe3.w, bm.w);
        __stcs(&o[base + 0 * stride_p + i], r0);
        __stcs(&o[base + 1 * stride_p + i], r1);
        __stcs(&o[base + 2 * stride_p + i], r2);
        __stcs(&o[base + 3 * stride_p + i], r3);
    }
}

// ---------------------------------------------------------------------------
// Inputs per metadata order:
// 0: ehr_vector (128*256)  1: criteria (32*64*256)  2: ec_mask (unused)
// 3: W_align (512)         4: b_align (unused, cancels in softmax)
// 5: W_mlp (512*256)       6: b_mlp (256)
// ---------------------------------------------------------------------------
extern "C" void kernel_launch(void* const* d_in, const int* in_sizes, int n_in,
                              void* d_out, int out_size) {
    const float* ehr     = (const float*)d_in[0];
    const float* crit    = (const float*)d_in[1];
    const float* W_align = (const float*)d_in[3];
    const float* W_mlp   = (const float*)d_in[5];
    const float* b_mlp   = (const float*)d_in[6];
    float* out = (float*)d_out;

    k_prep<<<C1_BLOCKS + ATT_BLOCKS + PE_BLOCKS, 256>>>(ehr, crit, W_align, W_mlp);
    k_main<<<BS1 * (BS2 / P_TILE), 256>>>(out, b_mlp);
}